// round 8
// baseline (speedup 1.0000x reference)
#include <cuda_runtime.h>
#include <cuda_bf16.h>

#define FEAT 128
#define MAX_NODES 50000

typedef unsigned int u32;

// ---------------- device scratch ----------------
static __device__ float g_agg[(size_t)MAX_NODES * FEAT];
// weight fragments, u32-packed per mma.m16n8k16 B-lane layout:
// idx = (((chunk*2+split)*4 + ks)*16 + nf)*64 + lane*2 + r
// -> per chunk: [hi 16KB][lo 16KB]
static __device__ __align__(16) u32 g_w1a_f[32768];  // K=256: 4 chunks
static __device__ __align__(16) u32 g_w1b_f[16384];  // K=128: 2 chunks
static __device__ __align__(16) u32 g_w2a_f[16384];
static __device__ __align__(16) u32 g_w2b_f[16384];

// ---- smem geometry (dynamic, bytes) ----
#define A_STRIDE  144
#define A_TILEB   18432
#define A_BUF     36864
#define WB0_OFF   73728
#define WB1_OFF   90112
#define DYN_BYTES 106496

// ---------------- helpers ----------------
__device__ __forceinline__ u32 smem_u32(const void* p) {
    u32 a;
    asm("{ .reg .u64 t; cvta.to.shared.u64 t, %1; cvt.u32.u64 %0, t; }" : "=r"(a) : "l"(p));
    return a;
}
__device__ __forceinline__ u32 lds32(u32 a) {
    u32 v;
    asm volatile("ld.shared.b32 %0, [%1];" : "=r"(v) : "r"(a));
    return v;
}
__device__ __forceinline__ void lds64(u32 a, u32& x, u32& y) {
    asm volatile("ld.shared.v2.b32 {%0,%1}, [%2];" : "=r"(x), "=r"(y) : "r"(a));
}
__device__ __forceinline__ void lds128(u32 a, u32* r) {
    asm volatile("ld.shared.v4.b32 {%0,%1,%2,%3}, [%4];"
                 : "=r"(r[0]), "=r"(r[1]), "=r"(r[2]), "=r"(r[3]) : "r"(a));
}
__device__ __forceinline__ void sts32(u32 a, u32 v) {
    asm volatile("st.shared.b32 [%0], %1;" ::"r"(a), "r"(v));
}
__device__ __forceinline__ void sts128(u32 a, const u32* r) {
    asm volatile("st.shared.v4.b32 [%0], {%1,%2,%3,%4};" ::"r"(a), "r"(r[0]), "r"(r[1]),
                 "r"(r[2]), "r"(r[3]));
}

__device__ __forceinline__ void mma16816(float c[4], const u32 a[4], u32 b0, u32 b1) {
    asm volatile(
        "mma.sync.aligned.m16n8k16.row.col.f32.bf16.bf16.f32 "
        "{%0,%1,%2,%3}, {%4,%5,%6,%7}, {%8,%9}, {%0,%1,%2,%3};"
        : "+f"(c[0]), "+f"(c[1]), "+f"(c[2]), "+f"(c[3])
        : "r"(a[0]), "r"(a[1]), "r"(a[2]), "r"(a[3]), "r"(b0), "r"(b1));
}

// fp32 pair -> packed bf16x2 hi + bf16x2 lo (x in low half)
__device__ __forceinline__ void split2(float x, float y, u32& h, u32& l) {
    asm("cvt.rn.bf16x2.f32 %0, %1, %2;" : "=r"(h) : "f"(y), "f"(x));
    float rx = x - __uint_as_float(h << 16);
    float ry = y - __uint_as_float(h & 0xFFFF0000u);
    asm("cvt.rn.bf16x2.f32 %0, %1, %2;" : "=r"(l) : "f"(ry), "f"(rx));
}

// convert 32 contiguous fp32 from global -> hi/lo bf16 into smem (byte addrs)
__device__ __forceinline__ void conv32(const float* __restrict__ rp, u32 dhi, u32 dlo) {
#pragma unroll
    for (int q = 0; q < 8; q++) {
        float4 f = __ldg((const float4*)rp + q);
        u32 h0, l0, h1, l1;
        split2(f.x, f.y, h0, l0);
        split2(f.z, f.w, h1, l1);
        sts32(dhi + q * 8, h0);
        sts32(dhi + q * 8 + 4, h1);
        sts32(dlo + q * 8, l0);
        sts32(dlo + q * 8 + 4, l1);
    }
}

// async-copy one 16KB weight split-tile global -> smem (256 threads)
__device__ __forceinline__ void cp_w16(const u32* __restrict__ g, u32 sB, int tid) {
#pragma unroll
    for (int i = 0; i < 4; i++) {
        u32 d = sB + (u32)(tid + i * 256) * 16;
        const u32* s = g + (tid + i * 256) * 4;
        asm volatile("cp.async.cg.shared.global [%0], [%1], 16;" ::"r"(d), "l"(s));
    }
    asm volatile("cp.async.commit_group;");
}
#define CP_WAIT1() asm volatile("cp.async.wait_group 1;" ::: "memory")
#define CP_WAIT0() asm volatile("cp.async.wait_group 0;" ::: "memory")

// ---- layer-1 GEMM phases, warp tile 64x32 (4 mt x 4 nf), A in padded tile ----
// phase A: B_hi -> hi@hi + lo@hi.  phase B: B_lo -> hi@lo.
__device__ __forceinline__ void g1_phaseA(u32 aHi, u32 wb, float (*acc)[4][4], int lane,
                                          int wc) {
    const u32 arow = aHi + (u32)(lane >> 2) * A_STRIDE + (lane & 3) * 4;
    const u32 bl = wb + (u32)wc * 1024 + lane * 8;
#pragma unroll
    for (int ks = 0; ks < 4; ks++) {
        u32 b[4][2];
#pragma unroll
        for (int nf = 0; nf < 4; nf++) lds64(bl + ks * 4096 + nf * 256, b[nf][0], b[nf][1]);
#pragma unroll
        for (int mt = 0; mt < 4; mt++) {
            u32 ab = arow + mt * (16 * A_STRIDE) + ks * 32;
            u32 ah[4], al[4];
            ah[0] = lds32(ab);
            ah[1] = lds32(ab + 8 * A_STRIDE);
            ah[2] = lds32(ab + 16);
            ah[3] = lds32(ab + 8 * A_STRIDE + 16);
            u32 ao = ab + A_TILEB;
            al[0] = lds32(ao);
            al[1] = lds32(ao + 8 * A_STRIDE);
            al[2] = lds32(ao + 16);
            al[3] = lds32(ao + 8 * A_STRIDE + 16);
#pragma unroll
            for (int nf = 0; nf < 4; nf++) {
                mma16816(acc[mt][nf], ah, b[nf][0], b[nf][1]);
                mma16816(acc[mt][nf], al, b[nf][0], b[nf][1]);
            }
        }
    }
}
__device__ __forceinline__ void g1_phaseB(u32 aHi, u32 wb, float (*acc)[4][4], int lane,
                                          int wc) {
    const u32 arow = aHi + (u32)(lane >> 2) * A_STRIDE + (lane & 3) * 4;
    const u32 bl = wb + (u32)wc * 1024 + lane * 8;
#pragma unroll
    for (int ks = 0; ks < 4; ks++) {
        u32 b[4][2];
#pragma unroll
        for (int nf = 0; nf < 4; nf++) lds64(bl + ks * 4096 + nf * 256, b[nf][0], b[nf][1]);
#pragma unroll
        for (int mt = 0; mt < 4; mt++) {
            u32 ab = arow + mt * (16 * A_STRIDE) + ks * 32;
            u32 ah[4];
            ah[0] = lds32(ab);
            ah[1] = lds32(ab + 8 * A_STRIDE);
            ah[2] = lds32(ab + 16);
            ah[3] = lds32(ab + 8 * A_STRIDE + 16);
#pragma unroll
            for (int nf = 0; nf < 4; nf++) mma16816(acc[mt][nf], ah, b[nf][0], b[nf][1]);
        }
    }
}

// ---- layer-2 GEMM phases, A from hidden fragments ----
// hidden slot addr: hb + (((split*2 + wr)*4 + mt)*8 + kg)*512 + lane*16
__device__ __forceinline__ void g2_phaseA(u32 hb, u32 wb, float (*acc)[4][4], int lane,
                                          int wr, int wc, int kg0) {
    const u32 bl = wb + (u32)wc * 1024 + lane * 8;
#pragma unroll
    for (int ks = 0; ks < 4; ks++) {
        int kg = kg0 + ks;
        u32 b[4][2];
#pragma unroll
        for (int nf = 0; nf < 4; nf++) lds64(bl + ks * 4096 + nf * 256, b[nf][0], b[nf][1]);
#pragma unroll
        for (int mt = 0; mt < 4; mt++) {
            u32 ah[4], al[4];
            lds128(hb + (u32)(((wr * 4 + mt) * 8 + kg) * 512) + lane * 16, ah);
            lds128(hb + (u32)((((2 + wr) * 4 + mt) * 8 + kg) * 512) + lane * 16, al);
#pragma unroll
            for (int nf = 0; nf < 4; nf++) {
                mma16816(acc[mt][nf], ah, b[nf][0], b[nf][1]);
                mma16816(acc[mt][nf], al, b[nf][0], b[nf][1]);
            }
        }
    }
}
__device__ __forceinline__ void g2_phaseB(u32 hb, u32 wb, float (*acc)[4][4], int lane,
                                          int wr, int wc, int kg0) {
    const u32 bl = wb + (u32)wc * 1024 + lane * 8;
#pragma unroll
    for (int ks = 0; ks < 4; ks++) {
        int kg = kg0 + ks;
        u32 b[4][2];
#pragma unroll
        for (int nf = 0; nf < 4; nf++) lds64(bl + ks * 4096 + nf * 256, b[nf][0], b[nf][1]);
#pragma unroll
        for (int mt = 0; mt < 4; mt++) {
            u32 ah[4];
            lds128(hb + (u32)(((wr * 4 + mt) * 8 + kg) * 512) + lane * 16, ah);
#pragma unroll
            for (int nf = 0; nf < 4; nf++) mma16816(acc[mt][nf], ah, b[nf][0], b[nf][1]);
        }
    }
}

// epilogue: relu(acc + bias) -> hidden fragments (direct A-frag layout); zero acc
__device__ __forceinline__ void epi_hidden(float (*acc)[4][4], const float* bias, u32 hb,
                                           int lane, int wr, int wc) {
    const int c2 = (lane & 3) * 2;
#pragma unroll
    for (int mt = 0; mt < 4; mt++) {
#pragma unroll
        for (int p = 0; p < 2; p++) {
            u32 h[4], l[4];
#pragma unroll
            for (int q = 0; q < 2; q++) {
                int nf = p * 2 + q;
                int n0 = wc * 32 + nf * 8 + c2;
                float v0 = fmaxf(acc[mt][nf][0] + bias[n0], 0.0f);
                float v1 = fmaxf(acc[mt][nf][1] + bias[n0 + 1], 0.0f);
                float v2 = fmaxf(acc[mt][nf][2] + bias[n0], 0.0f);
                float v3 = fmaxf(acc[mt][nf][3] + bias[n0 + 1], 0.0f);
                split2(v0, v1, h[q * 2], l[q * 2]);
                split2(v2, v3, h[q * 2 + 1], l[q * 2 + 1]);
            }
            int kg = wc * 2 + p;
            sts128(hb + (u32)(((wr * 4 + mt) * 8 + kg) * 512) + lane * 16, h);
            sts128(hb + (u32)((((2 + wr) * 4 + mt) * 8 + kg) * 512) + lane * 16, l);
        }
#pragma unroll
        for (int nf = 0; nf < 4; nf++)
#pragma unroll
            for (int j = 0; j < 4; j++) acc[mt][nf][j] = 0.0f;
    }
}

// ---------------- kernel 0: weight prep (split + fragment pack) ----------------
__device__ __forceinline__ int fidx(int ke, int n, int split) {
    int chunk = ke >> 6, ks = (ke >> 4) & 3, r = (ke >> 3) & 1, l4 = (ke >> 1) & 3;
    int nf = n >> 3, lane = (n & 7) * 4 + l4;
    return (((chunk * 2 + split) * 4 + ks) * 16 + nf) * 64 + lane * 2 + r;
}

__global__ void prep_weights(const float* __restrict__ W1a, const float* __restrict__ W1b,
                             const float* __restrict__ W2a, const float* __restrict__ W2b) {
    int total = 16384 + 3 * 8192;
    for (int i = blockIdx.x * blockDim.x + threadIdx.x; i < total;
         i += gridDim.x * blockDim.x) {
        int j = i;
        const float* W;
        u32* G;
        if (j < 16384) {
            W = W1a;
            G = g_w1a_f;
        } else {
            j -= 16384;
            int ws = j / 8192;
            j %= 8192;
            W = (ws == 0) ? W1b : (ws == 1) ? W2a : W2b;
            G = (ws == 0) ? g_w1b_f : (ws == 1) ? g_w2a_f : g_w2b_f;
        }
        int ke = (j >> 7) * 2, n = j & 127;
        float x0 = W[ke * 128 + n], x1 = W[(ke + 1) * 128 + n];
        u32 H, L;
        split2(x0, x1, H, L);
        G[fidx(ke, n, 0)] = H;
        G[fidx(ke, n, 1)] = L;
    }
}

// ---------------- kernel 1: g_agg = node_feats ----------------
__global__ void init_agg_kernel(const float* __restrict__ node_feats, int total4) {
    int i = blockIdx.x * blockDim.x + threadIdx.x;
    int stride = gridDim.x * blockDim.x;
    const float4* s = (const float4*)node_feats;
    float4* d = (float4*)g_agg;
    for (; i < total4; i += stride) d[i] = s[i];
}

// ---------------- kernel 2: edge MLP + scatter ----------------
extern __shared__ char dynraw[];

__global__ __launch_bounds__(256, 2) void edge_kernel(
    const float* __restrict__ node_feats, const float* __restrict__ edge_feats,
    const int* __restrict__ src, const int* __restrict__ dst,
    const float* __restrict__ b1a, const float* __restrict__ b1b, int n_edges) {
    __shared__ int s_src[128], s_dst[128];
    __shared__ float s_ba[FEAT], s_bb[FEAT];

    const int tid = threadIdx.x;
    const int wid = tid >> 5, lane = tid & 31;
    const int wr = wid >> 2, wc = wid & 3;
    const u32 smb = smem_u32(dynraw);
    const u32 hb = smb;  // hidden fragments alias A region
    const u32 wb0 = smb + WB0_OFF, wb1 = smb + WB1_OFF;

    const int e0 = blockIdx.x * 128;
    if (tid < 128) {
        int e = min(e0 + tid, n_edges - 1);
        s_src[tid] = __ldg(src + e);
        s_dst[tid] = __ldg(dst + e);
        s_ba[tid] = __ldg(b1a + tid);
        s_bb[tid] = __ldg(b1b + tid);
    }
    cp_w16(g_w1a_f, wb0, tid);  // hi_0
    __syncthreads();

    float acc[4][4][4];
#pragma unroll
    for (int mt = 0; mt < 4; mt++)
#pragma unroll
        for (int nf = 0; nf < 4; nf++)
#pragma unroll
            for (int j = 0; j < 4; j++) acc[mt][nf][j] = 0.0f;

    const int row = tid >> 1, kh = tid & 1;

    // conv chunk 0 (node_feats part 0)
    {
        const float* rp = node_feats + (size_t)s_src[row] * FEAT + kh * 32;
        u32 d = smb + (u32)row * A_STRIDE + kh * 64;
        conv32(rp, d, d + A_TILEB);
    }

    const u32 aWarp0 = smb + (u32)wr * 64 * A_STRIDE;

    // ---- layer 1: K=256, 4 chunks ----
#pragma unroll 1
    for (int c = 0; c < 4; c++) {
        cp_w16(g_w1a_f + c * 8192 + 4096, wb1, tid);  // lo_c (wb1 free: end-sync)
        CP_WAIT1();                                   // hi_c landed
        __syncthreads();
        u32 aHi = aWarp0 + (u32)(c & 1) * A_BUF;
        g1_phaseA(aHi, wb0, acc, lane, wc);
        __syncthreads();  // ALL warps done reading wb0 before overwrite
        const u32* nxt = (c < 3) ? (g_w1a_f + (c + 1) * 8192) : g_w1b_f;
        cp_w16(nxt, wb0, tid);  // hi_{c+1} (or layer2 hi_0)
        if (c < 3) {            // conv next chunk into other A buffer (overlaps cp)
            const float* rp;
            int c1 = c + 1;
            if (c1 < 2)
                rp = node_feats + (size_t)s_src[row] * FEAT + c1 * 64 + kh * 32;
            else
                rp = edge_feats + (size_t)min(e0 + row, n_edges - 1) * FEAT +
                     (c1 - 2) * 64 + kh * 32;
            u32 d = smb + (u32)(c1 & 1) * A_BUF + (u32)row * A_STRIDE + kh * 64;
            conv32(rp, d, d + A_TILEB);
        }
        CP_WAIT1();  // lo_c landed
        __syncthreads();
        g1_phaseB(aHi, wb1, acc, lane, wc);
        __syncthreads();  // ALL warps done reading wb1 (and A) before reuse
    }

    // ---- epilogue 1: relu -> hidden fragments (A reads done: loop-end sync) ----
    epi_hidden(acc, s_ba, hb, lane, wr, wc);

    // ---- layer 2: K=128, 2 chunks ----
#pragma unroll 1
    for (int c = 0; c < 2; c++) {
        cp_w16(g_w1b_f + c * 8192 + 4096, wb1, tid);  // lo_c
        CP_WAIT1();
        __syncthreads();  // also orders epi_hidden writes before g2 reads
        g2_phaseA(hb, wb0, acc, lane, wr, wc, c * 4);
        if (c == 0) {
            __syncthreads();  // wb0 readers done
            cp_w16(g_w1b_f + 8192, wb0, tid);
            CP_WAIT1();
        } else {
            CP_WAIT0();
        }
        __syncthreads();
        g2_phaseB(hb, wb1, acc, lane, wr, wc, c * 4);
        __syncthreads();  // wb1 readers done before next-iter overwrite
    }

    // ---- epilogue 2: scatter (acc + b1b) into g_agg ----
    const int rr = lane >> 2, c2 = (lane & 3) * 2;
#pragma unroll
    for (int mt = 0; mt < 4; mt++) {
        const int r0 = wr * 64 + mt * 16 + rr, r1 = r0 + 8;
        float* p0 = g_agg + (size_t)s_dst[r0] * FEAT;
        float* p1 = g_agg + (size_t)s_dst[r1] * FEAT;
        const bool ok0 = (e0 + r0 < n_edges), ok1 = (e0 + r1 < n_edges);
#pragma unroll
        for (int nf = 0; nf < 4; nf++) {
            int n0 = wc * 32 + nf * 8 + c2;
            if (ok0) {
                atomicAdd(p0 + n0, acc[mt][nf][0] + s_bb[n0]);
                atomicAdd(p0 + n0 + 1, acc[mt][nf][1] + s_bb[n0 + 1]);
            }
            if (ok1) {
                atomicAdd(p1 + n0, acc[mt][nf][2] + s_bb[n0]);
                atomicAdd(p1 + n0 + 1, acc[mt][nf][3] + s_bb[n0 + 1]);
            }
        }
    }
}

// ---------------- kernel 3: node MLP ----------------
__global__ __launch_bounds__(256, 2) void node_kernel(const float* __restrict__ b2a,
                                                      const float* __restrict__ b2b,
                                                      float* __restrict__ out, int n_nodes) {
    __shared__ float s_ba[FEAT], s_bb[FEAT];

    const int tid = threadIdx.x;
    const int wid = tid >> 5, lane = tid & 31;
    const int wr = wid >> 2, wc = wid & 3;
    const u32 smb = smem_u32(dynraw);
    const u32 hb = smb;
    const u32 wb0 = smb + WB0_OFF, wb1 = smb + WB1_OFF;

    const int v0 = blockIdx.x * 128;
    if (tid < 128) {
        s_ba[tid] = __ldg(b2a + tid);
        s_bb[tid] = __ldg(b2b + tid);
    }
    cp_w16(g_w2a_f, wb0, tid);
    __syncthreads();

    float acc[4][4][4];
#pragma unroll
    for (int mt = 0; mt < 4; mt++)
#pragma unroll
        for (int nf = 0; nf < 4; nf++)
#pragma unroll
            for (int j = 0; j < 4; j++) acc[mt][nf][j] = 0.0f;

    const int row = tid >> 1, kh = tid & 1;
    const size_t grow = (size_t)min(v0 + row, n_nodes - 1) * FEAT;

    {
        const float* rp = g_agg + grow + kh * 32;
        u32 d = smb + (u32)row * A_STRIDE + kh * 64;
        conv32(rp, d, d + A_TILEB);
    }

    const u32 aWarp0 = smb + (u32)wr * 64 * A_STRIDE;

    // ---- layer 1: K=128, 2 chunks ----
#pragma unroll 1
    for (int c = 0; c < 2; c++) {
        cp_w16(g_w2a_f + c * 8192 + 4096, wb1, tid);
        CP_WAIT1();
        __syncthreads();
        u32 aHi = aWarp0 + (u32)(c & 1) * A_BUF;
        g1_phaseA(aHi, wb0, acc, lane, wc);
        __syncthreads();  // wb0 readers done
        const u32* nxt = (c == 0) ? (g_w2a_f + 8192) : g_w2b_f;
        cp_w16(nxt, wb0, tid);
        if (c == 0) {
            const float* rp = g_agg + grow + 64 + kh * 32;
            u32 d = smb + A_BUF + (u32)row * A_STRIDE + kh * 64;
            conv32(rp, d, d + A_TILEB);
        }
        CP_WAIT1();
        __syncthreads();
        g1_phaseB(aHi, wb1, acc, lane, wc);
        __syncthreads();  // wb1 + A readers done
    }

    epi_hidden(acc, s_ba, hb, lane, wr, wc);

    // ---- layer 2: K=128, 2 chunks ----
#pragma unroll 1
    for (int c = 0; c < 2; c++) {
        cp_w16(g_w2b_f + c * 8192 + 4096, wb1, tid);
        CP_WAIT1();
        __syncthreads();
        g2_phaseA(hb, wb0, acc, lane, wr, wc, c * 4);
        if (c == 0) {
            __syncthreads();
            cp_w16(g_w2b_f + 8192, wb0, tid);
            CP_WAIT1();
        } else {
            CP_WAIT0();
        }
        __syncthreads();
        g2_phaseB(hb, wb1, acc, lane, wr, wc, c * 4);
        __syncthreads();
    }

    // ---- epilogue 2: out = acc + b2b ----
    const int rr = lane >> 2, c2 = (lane & 3) * 2;
#pragma unroll
    for (int mt = 0; mt < 4; mt++) {
        const int r0 = wr * 64 + mt * 16 + rr, r1 = r0 + 8;
#pragma unroll
        for (int nf = 0; nf < 4; nf++) {
            int n0 = wc * 32 + nf * 8 + c2;
            if (v0 + r0 < n_nodes) {
                float2 v = make_float2(acc[mt][nf][0] + s_bb[n0],
                                       acc[mt][nf][1] + s_bb[n0 + 1]);
                *(float2*)(out + (size_t)(v0 + r0) * FEAT + n0) = v;
            }
            if (v0 + r1 < n_nodes) {
                float2 v = make_float2(acc[mt][nf][2] + s_bb[n0],
                                       acc[mt][nf][3] + s_bb[n0 + 1]);
                *(float2*)(out + (size_t)(v0 + r1) * FEAT + n0) = v;
            }
        }
    }
}

// ---------------- launch ----------------
extern "C" void kernel_launch(void* const* d_in, const int* in_sizes, int n_in,
                              void* d_out, int out_size) {
    const float* node_feats = (const float*)d_in[0];
    const float* edge_feats = (const float*)d_in[1];
    const int* src = (const int*)d_in[2];
    const int* dst = (const int*)d_in[3];
    const float* W1a = (const float*)d_in[4];
    const float* b1a = (const float*)d_in[5];
    const float* W1b = (const float*)d_in[6];
    const float* b1b = (const float*)d_in[7];
    const float* W2a = (const float*)d_in[8];
    const float* b2a = (const float*)d_in[9];
    const float* W2b = (const float*)d_in[10];
    const float* b2b = (const float*)d_in[11];
    float* out = (float*)d_out;

    const int n_nodes = in_sizes[0] / FEAT;
    const int n_edges = in_sizes[2];

    cudaFuncSetAttribute(edge_kernel, cudaFuncAttributeMaxDynamicSharedMemorySize,
                         DYN_BYTES);
    cudaFuncSetAttribute(node_kernel, cudaFuncAttributeMaxDynamicSharedMemorySize,
                         DYN_BYTES);

    prep_weights<<<160, 256>>>(W1a, W1b, W2a, W2b);
    init_agg_kernel<<<512, 256>>>(node_feats, n_nodes * (FEAT / 4));

    int edge_blocks = (n_edges + 127) / 128;
    edge_kernel<<<edge_blocks, 256, DYN_BYTES>>>(node_feats, edge_feats, src, dst, b1a,
                                                 b1b, n_edges);

    int node_blocks = (n_nodes + 127) / 128;
    node_kernel<<<node_blocks, 256, DYN_BYTES>>>(b2a, b2b, out, n_nodes);
}

// round 9
// speedup vs baseline: 1.0290x; 1.0290x over previous
#include <cuda_runtime.h>
#include <cuda_bf16.h>

#define FEAT 128
#define MAX_NODES 50000

typedef unsigned int u32;

// ---------------- device scratch ----------------
static __device__ float g_agg[(size_t)MAX_NODES * FEAT];
// weight fragments, u32-packed per mma.m16n8k16 B-lane layout:
// idx = (((chunk*2+split)*4 + ks)*16 + nf)*64 + lane*2 + r
// -> per chunk: [hi 16KB][lo 16KB]
static __device__ __align__(16) u32 g_w1a_f[32768];  // K=256: 4 chunks
static __device__ __align__(16) u32 g_w1b_f[16384];  // K=128: 2 chunks
static __device__ __align__(16) u32 g_w2a_f[16384];
static __device__ __align__(16) u32 g_w2b_f[16384];

// ---- smem geometry (dynamic, bytes) ----
#define A_STRIDE  144
#define A_TILEB   18432
#define A_BUF     36864
#define WB0_OFF   73728
#define WB1_OFF   90112
#define DYN_BYTES 106496

// ---------------- helpers ----------------
__device__ __forceinline__ u32 smem_u32(const void* p) {
    u32 a;
    asm("{ .reg .u64 t; cvta.to.shared.u64 t, %1; cvt.u32.u64 %0, t; }" : "=r"(a) : "l"(p));
    return a;
}
__device__ __forceinline__ u32 lds32(u32 a) {
    u32 v;
    asm volatile("ld.shared.b32 %0, [%1];" : "=r"(v) : "r"(a));
    return v;
}
__device__ __forceinline__ void lds64(u32 a, u32& x, u32& y) {
    asm volatile("ld.shared.v2.b32 {%0,%1}, [%2];" : "=r"(x), "=r"(y) : "r"(a));
}
__device__ __forceinline__ void lds128(u32 a, u32* r) {
    asm volatile("ld.shared.v4.b32 {%0,%1,%2,%3}, [%4];"
                 : "=r"(r[0]), "=r"(r[1]), "=r"(r[2]), "=r"(r[3]) : "r"(a));
}
__device__ __forceinline__ void sts32(u32 a, u32 v) {
    asm volatile("st.shared.b32 [%0], %1;" ::"r"(a), "r"(v));
}
__device__ __forceinline__ void sts128(u32 a, const u32* r) {
    asm volatile("st.shared.v4.b32 [%0], {%1,%2,%3,%4};" ::"r"(a), "r"(r[0]), "r"(r[1]),
                 "r"(r[2]), "r"(r[3]));
}

__device__ __forceinline__ void mma16816(float c[4], const u32 a[4], u32 b0, u32 b1) {
    asm volatile(
        "mma.sync.aligned.m16n8k16.row.col.f32.bf16.bf16.f32 "
        "{%0,%1,%2,%3}, {%4,%5,%6,%7}, {%8,%9}, {%0,%1,%2,%3};"
        : "+f"(c[0]), "+f"(c[1]), "+f"(c[2]), "+f"(c[3])
        : "r"(a[0]), "r"(a[1]), "r"(a[2]), "r"(a[3]), "r"(b0), "r"(b1));
}

// fp32 pair -> packed bf16x2 hi + bf16x2 lo (x in low half)
__device__ __forceinline__ void split2(float x, float y, u32& h, u32& l) {
    asm("cvt.rn.bf16x2.f32 %0, %1, %2;" : "=r"(h) : "f"(y), "f"(x));
    float rx = x - __uint_as_float(h << 16);
    float ry = y - __uint_as_float(h & 0xFFFF0000u);
    asm("cvt.rn.bf16x2.f32 %0, %1, %2;" : "=r"(l) : "f"(ry), "f"(rx));
}

// convert 32 contiguous fp32 from global -> hi/lo bf16 into smem (byte addrs)
__device__ __forceinline__ void conv32(const float* __restrict__ rp, u32 dhi, u32 dlo) {
#pragma unroll
    for (int q = 0; q < 8; q++) {
        float4 f = __ldg((const float4*)rp + q);
        u32 h0, l0, h1, l1;
        split2(f.x, f.y, h0, l0);
        split2(f.z, f.w, h1, l1);
        sts32(dhi + q * 8, h0);
        sts32(dhi + q * 8 + 4, h1);
        sts32(dlo + q * 8, l0);
        sts32(dlo + q * 8 + 4, l1);
    }
}

// async-copy one 16KB weight split-tile global -> smem (256 threads)
__device__ __forceinline__ void cp_w16(const u32* __restrict__ g, u32 sB, int tid) {
#pragma unroll
    for (int i = 0; i < 4; i++) {
        u32 d = sB + (u32)(tid + i * 256) * 16;
        const u32* s = g + (tid + i * 256) * 4;
        asm volatile("cp.async.cg.shared.global [%0], [%1], 16;" ::"r"(d), "l"(s));
    }
    asm volatile("cp.async.commit_group;");
}
#define CP_WAIT0() asm volatile("cp.async.wait_group 0;" ::: "memory")

// ---- fused layer-1 GEMM chunk: acc += A_hi*B_hi + A_hi*B_lo + A_lo*B_hi ----
// warp tile 64x32 (4 mt x 4 nf); A in padded-row tile; both B splits resident.
// MMAs grouped into independent passes of 8 (no accumulator RAW within a pass).
__device__ __forceinline__ void g1_fused(u32 aHi, u32 wbh, u32 wbl, float (*acc)[4][4],
                                         int lane, int wc) {
    const u32 arow = aHi + (u32)(lane >> 2) * A_STRIDE + (lane & 3) * 4;
    const u32 blh = wbh + (u32)wc * 1024 + lane * 8;
    const u32 bll = wbl + (u32)wc * 1024 + lane * 8;
#pragma unroll
    for (int ks = 0; ks < 4; ks++) {
        u32 bh[4][2], bl[4][2];
#pragma unroll
        for (int nf = 0; nf < 4; nf++) {
            lds64(blh + ks * 4096 + nf * 256, bh[nf][0], bh[nf][1]);
            lds64(bll + ks * 4096 + nf * 256, bl[nf][0], bl[nf][1]);
        }
#pragma unroll
        for (int mg = 0; mg < 2; mg++) {  // mt groups {0,1}, {2,3}
            u32 ah[2][4], al[2][4];
#pragma unroll
            for (int m = 0; m < 2; m++) {
                u32 ab = arow + (mg * 2 + m) * (16 * A_STRIDE) + ks * 32;
                ah[m][0] = lds32(ab);
                ah[m][1] = lds32(ab + 8 * A_STRIDE);
                ah[m][2] = lds32(ab + 16);
                ah[m][3] = lds32(ab + 8 * A_STRIDE + 16);
                u32 ao = ab + A_TILEB;
                al[m][0] = lds32(ao);
                al[m][1] = lds32(ao + 8 * A_STRIDE);
                al[m][2] = lds32(ao + 16);
                al[m][3] = lds32(ao + 8 * A_STRIDE + 16);
            }
            // pass 1: hi @ B_hi (8 independent accs)
#pragma unroll
            for (int m = 0; m < 2; m++)
#pragma unroll
                for (int nf = 0; nf < 4; nf++)
                    mma16816(acc[mg * 2 + m][nf], ah[m], bh[nf][0], bh[nf][1]);
            // pass 2: hi @ B_lo
#pragma unroll
            for (int m = 0; m < 2; m++)
#pragma unroll
                for (int nf = 0; nf < 4; nf++)
                    mma16816(acc[mg * 2 + m][nf], ah[m], bl[nf][0], bl[nf][1]);
            // pass 3: lo @ B_hi
#pragma unroll
            for (int m = 0; m < 2; m++)
#pragma unroll
                for (int nf = 0; nf < 4; nf++)
                    mma16816(acc[mg * 2 + m][nf], al[m], bh[nf][0], bh[nf][1]);
        }
    }
}

// ---- fused layer-2 GEMM chunk: A from hidden fragments (LDS.128) ----
// hidden slot addr: hb + (((split*2 + wr)*4 + mt)*8 + kg)*512 + lane*16
__device__ __forceinline__ void g2_fused(u32 hb, u32 wbh, u32 wbl, float (*acc)[4][4],
                                         int lane, int wr, int wc, int kg0) {
    const u32 blh = wbh + (u32)wc * 1024 + lane * 8;
    const u32 bll = wbl + (u32)wc * 1024 + lane * 8;
#pragma unroll
    for (int ks = 0; ks < 4; ks++) {
        int kg = kg0 + ks;
        u32 bh[4][2], bl[4][2];
#pragma unroll
        for (int nf = 0; nf < 4; nf++) {
            lds64(blh + ks * 4096 + nf * 256, bh[nf][0], bh[nf][1]);
            lds64(bll + ks * 4096 + nf * 256, bl[nf][0], bl[nf][1]);
        }
#pragma unroll
        for (int mg = 0; mg < 2; mg++) {
            u32 ah[2][4], al[2][4];
#pragma unroll
            for (int m = 0; m < 2; m++) {
                int mt = mg * 2 + m;
                lds128(hb + (u32)(((wr * 4 + mt) * 8 + kg) * 512) + lane * 16, ah[m]);
                lds128(hb + (u32)((((2 + wr) * 4 + mt) * 8 + kg) * 512) + lane * 16,
                       al[m]);
            }
#pragma unroll
            for (int m = 0; m < 2; m++)
#pragma unroll
                for (int nf = 0; nf < 4; nf++)
                    mma16816(acc[mg * 2 + m][nf], ah[m], bh[nf][0], bh[nf][1]);
#pragma unroll
            for (int m = 0; m < 2; m++)
#pragma unroll
                for (int nf = 0; nf < 4; nf++)
                    mma16816(acc[mg * 2 + m][nf], ah[m], bl[nf][0], bl[nf][1]);
#pragma unroll
            for (int m = 0; m < 2; m++)
#pragma unroll
                for (int nf = 0; nf < 4; nf++)
                    mma16816(acc[mg * 2 + m][nf], al[m], bh[nf][0], bh[nf][1]);
        }
    }
}

// epilogue: relu(acc + bias) -> hidden fragments (direct A-frag layout); zero acc
__device__ __forceinline__ void epi_hidden(float (*acc)[4][4], const float* bias, u32 hb,
                                           int lane, int wr, int wc) {
    const int c2 = (lane & 3) * 2;
#pragma unroll
    for (int mt = 0; mt < 4; mt++) {
#pragma unroll
        for (int p = 0; p < 2; p++) {
            u32 h[4], l[4];
#pragma unroll
            for (int q = 0; q < 2; q++) {
                int nf = p * 2 + q;
                int n0 = wc * 32 + nf * 8 + c2;
                float v0 = fmaxf(acc[mt][nf][0] + bias[n0], 0.0f);
                float v1 = fmaxf(acc[mt][nf][1] + bias[n0 + 1], 0.0f);
                float v2 = fmaxf(acc[mt][nf][2] + bias[n0], 0.0f);
                float v3 = fmaxf(acc[mt][nf][3] + bias[n0 + 1], 0.0f);
                split2(v0, v1, h[q * 2], l[q * 2]);
                split2(v2, v3, h[q * 2 + 1], l[q * 2 + 1]);
            }
            int kg = wc * 2 + p;
            sts128(hb + (u32)(((wr * 4 + mt) * 8 + kg) * 512) + lane * 16, h);
            sts128(hb + (u32)((((2 + wr) * 4 + mt) * 8 + kg) * 512) + lane * 16, l);
        }
#pragma unroll
        for (int nf = 0; nf < 4; nf++)
#pragma unroll
            for (int j = 0; j < 4; j++) acc[mt][nf][j] = 0.0f;
    }
}

// ---------------- kernel 0: weight prep (split + fragment pack) ----------------
__device__ __forceinline__ int fidx(int ke, int n, int split) {
    int chunk = ke >> 6, ks = (ke >> 4) & 3, r = (ke >> 3) & 1, l4 = (ke >> 1) & 3;
    int nf = n >> 3, lane = (n & 7) * 4 + l4;
    return (((chunk * 2 + split) * 4 + ks) * 16 + nf) * 64 + lane * 2 + r;
}

__global__ void prep_weights(const float* __restrict__ W1a, const float* __restrict__ W1b,
                             const float* __restrict__ W2a, const float* __restrict__ W2b) {
    int total = 16384 + 3 * 8192;
    for (int i = blockIdx.x * blockDim.x + threadIdx.x; i < total;
         i += gridDim.x * blockDim.x) {
        int j = i;
        const float* W;
        u32* G;
        if (j < 16384) {
            W = W1a;
            G = g_w1a_f;
        } else {
            j -= 16384;
            int ws = j / 8192;
            j %= 8192;
            W = (ws == 0) ? W1b : (ws == 1) ? W2a : W2b;
            G = (ws == 0) ? g_w1b_f : (ws == 1) ? g_w2a_f : g_w2b_f;
        }
        int ke = (j >> 7) * 2, n = j & 127;
        float x0 = W[ke * 128 + n], x1 = W[(ke + 1) * 128 + n];
        u32 H, L;
        split2(x0, x1, H, L);
        G[fidx(ke, n, 0)] = H;
        G[fidx(ke, n, 1)] = L;
    }
}

// ---------------- kernel 1: g_agg = node_feats ----------------
__global__ void init_agg_kernel(const float* __restrict__ node_feats, int total4) {
    int i = blockIdx.x * blockDim.x + threadIdx.x;
    int stride = gridDim.x * blockDim.x;
    const float4* s = (const float4*)node_feats;
    float4* d = (float4*)g_agg;
    for (; i < total4; i += stride) d[i] = s[i];
}

// ---------------- kernel 2: edge MLP + scatter ----------------
extern __shared__ char dynraw[];

__global__ __launch_bounds__(256, 2) void edge_kernel(
    const float* __restrict__ node_feats, const float* __restrict__ edge_feats,
    const int* __restrict__ src, const int* __restrict__ dst,
    const float* __restrict__ b1a, const float* __restrict__ b1b, int n_edges) {
    __shared__ int s_src[128], s_dst[128];
    __shared__ float s_ba[FEAT], s_bb[FEAT];

    const int tid = threadIdx.x;
    const int wid = tid >> 5, lane = tid & 31;
    const int wr = wid >> 2, wc = wid & 3;
    const u32 smb = smem_u32(dynraw);
    const u32 hb = smb;  // hidden fragments alias A region
    const u32 wb0 = smb + WB0_OFF, wb1 = smb + WB1_OFF;

    const int e0 = blockIdx.x * 128;
    if (tid < 128) {
        int e = min(e0 + tid, n_edges - 1);
        s_src[tid] = __ldg(src + e);
        s_dst[tid] = __ldg(dst + e);
        s_ba[tid] = __ldg(b1a + tid);
        s_bb[tid] = __ldg(b1b + tid);
    }
    __syncthreads();

    float acc[4][4][4];
#pragma unroll
    for (int mt = 0; mt < 4; mt++)
#pragma unroll
        for (int nf = 0; nf < 4; nf++)
#pragma unroll
            for (int j = 0; j < 4; j++) acc[mt][nf][j] = 0.0f;

    const int row = tid >> 1, kh = tid & 1;
    const u32 aWarp0 = smb + (u32)wr * 64 * A_STRIDE;

    // conv chunk 0 (node_feats part 0) into A0
    {
        const float* rp = node_feats + (size_t)s_src[row] * FEAT + kh * 32;
        u32 d = smb + (u32)row * A_STRIDE + kh * 64;
        conv32(rp, d, d + A_TILEB);
    }

    // ---- layer 1: K=256, 4 chunks (fused splits, 2 syncs/chunk) ----
#pragma unroll 1
    for (int c = 0; c < 4; c++) {
        cp_w16(g_w1a_f + c * 8192, wb0, tid);         // hi_c
        cp_w16(g_w1a_f + c * 8192 + 4096, wb1, tid);  // lo_c
        if (c < 3) {  // conv next chunk into other A buffer (overlaps cp)
            const float* rp;
            int c1 = c + 1;
            if (c1 < 2)
                rp = node_feats + (size_t)s_src[row] * FEAT + c1 * 64 + kh * 32;
            else
                rp = edge_feats + (size_t)min(e0 + row, n_edges - 1) * FEAT +
                     (c1 - 2) * 64 + kh * 32;
            u32 d = smb + (u32)(c1 & 1) * A_BUF + (u32)row * A_STRIDE + kh * 64;
            conv32(rp, d, d + A_TILEB);
        }
        CP_WAIT0();
        __syncthreads();  // weights c + A(c) (and A(c+1) stores) visible
        g1_fused(aWarp0 + (u32)(c & 1) * A_BUF, wb0, wb1, acc, lane, wc);
        __syncthreads();  // all warps done reading wb/A before reuse
    }

    // ---- epilogue 1: relu -> hidden fragments (A region free after loop sync) ----
    epi_hidden(acc, s_ba, hb, lane, wr, wc);

    // ---- layer 2: K=128, 2 chunks ----
#pragma unroll 1
    for (int c = 0; c < 2; c++) {
        cp_w16(g_w1b_f + c * 8192, wb0, tid);
        cp_w16(g_w1b_f + c * 8192 + 4096, wb1, tid);
        CP_WAIT0();
        __syncthreads();  // also orders epi_hidden writes before g2 reads
        g2_fused(hb, wb0, wb1, acc, lane, wr, wc, c * 4);
        __syncthreads();
    }

    // ---- epilogue 2: scatter (acc + b1b) into g_agg ----
    const int rr = lane >> 2, c2 = (lane & 3) * 2;
#pragma unroll
    for (int mt = 0; mt < 4; mt++) {
        const int r0 = wr * 64 + mt * 16 + rr, r1 = r0 + 8;
        float* p0 = g_agg + (size_t)s_dst[r0] * FEAT;
        float* p1 = g_agg + (size_t)s_dst[r1] * FEAT;
        const bool ok0 = (e0 + r0 < n_edges), ok1 = (e0 + r1 < n_edges);
#pragma unroll
        for (int nf = 0; nf < 4; nf++) {
            int n0 = wc * 32 + nf * 8 + c2;
            if (ok0) {
                atomicAdd(p0 + n0, acc[mt][nf][0] + s_bb[n0]);
                atomicAdd(p0 + n0 + 1, acc[mt][nf][1] + s_bb[n0 + 1]);
            }
            if (ok1) {
                atomicAdd(p1 + n0, acc[mt][nf][2] + s_bb[n0]);
                atomicAdd(p1 + n0 + 1, acc[mt][nf][3] + s_bb[n0 + 1]);
            }
        }
    }
}

// ---------------- kernel 3: node MLP ----------------
__global__ __launch_bounds__(256, 2) void node_kernel(const float* __restrict__ b2a,
                                                      const float* __restrict__ b2b,
                                                      float* __restrict__ out, int n_nodes) {
    __shared__ float s_ba[FEAT], s_bb[FEAT];

    const int tid = threadIdx.x;
    const int wid = tid >> 5, lane = tid & 31;
    const int wr = wid >> 2, wc = wid & 3;
    const u32 smb = smem_u32(dynraw);
    const u32 hb = smb;
    const u32 wb0 = smb + WB0_OFF, wb1 = smb + WB1_OFF;

    const int v0 = blockIdx.x * 128;
    if (tid < 128) {
        s_ba[tid] = __ldg(b2a + tid);
        s_bb[tid] = __ldg(b2b + tid);
    }
    __syncthreads();

    float acc[4][4][4];
#pragma unroll
    for (int mt = 0; mt < 4; mt++)
#pragma unroll
        for (int nf = 0; nf < 4; nf++)
#pragma unroll
            for (int j = 0; j < 4; j++) acc[mt][nf][j] = 0.0f;

    const int row = tid >> 1, kh = tid & 1;
    const size_t grow = (size_t)min(v0 + row, n_nodes - 1) * FEAT;
    const u32 aWarp0 = smb + (u32)wr * 64 * A_STRIDE;

    {
        const float* rp = g_agg + grow + kh * 32;
        u32 d = smb + (u32)row * A_STRIDE + kh * 64;
        conv32(rp, d, d + A_TILEB);
    }

    // ---- layer 1: K=128, 2 chunks ----
#pragma unroll 1
    for (int c = 0; c < 2; c++) {
        cp_w16(g_w2a_f + c * 8192, wb0, tid);
        cp_w16(g_w2a_f + c * 8192 + 4096, wb1, tid);
        if (c == 0) {
            const float* rp = g_agg + grow + 64 + kh * 32;
            u32 d = smb + A_BUF + (u32)row * A_STRIDE + kh * 64;
            conv32(rp, d, d + A_TILEB);
        }
        CP_WAIT0();
        __syncthreads();
        g1_fused(aWarp0 + (u32)(c & 1) * A_BUF, wb0, wb1, acc, lane, wc);
        __syncthreads();
    }

    epi_hidden(acc, s_ba, hb, lane, wr, wc);

    // ---- layer 2: K=128, 2 chunks ----
#pragma unroll 1
    for (int c = 0; c < 2; c++) {
        cp_w16(g_w2b_f + c * 8192, wb0, tid);
        cp_w16(g_w2b_f + c * 8192 + 4096, wb1, tid);
        CP_WAIT0();
        __syncthreads();
        g2_fused(hb, wb0, wb1, acc, lane, wr, wc, c * 4);
        __syncthreads();
    }

    // ---- epilogue 2: out = acc + b2b ----
    const int rr = lane >> 2, c2 = (lane & 3) * 2;
#pragma unroll
    for (int mt = 0; mt < 4; mt++) {
        const int r0 = wr * 64 + mt * 16 + rr, r1 = r0 + 8;
#pragma unroll
        for (int nf = 0; nf < 4; nf++) {
            int n0 = wc * 32 + nf * 8 + c2;
            if (v0 + r0 < n_nodes) {
                float2 v = make_float2(acc[mt][nf][0] + s_bb[n0],
                                       acc[mt][nf][1] + s_bb[n0 + 1]);
                *(float2*)(out + (size_t)(v0 + r0) * FEAT + n0) = v;
            }
            if (v0 + r1 < n_nodes) {
                float2 v = make_float2(acc[mt][nf][2] + s_bb[n0],
                                       acc[mt][nf][3] + s_bb[n0 + 1]);
                *(float2*)(out + (size_t)(v0 + r1) * FEAT + n0) = v;
            }
        }
    }
}

// ---------------- launch ----------------
extern "C" void kernel_launch(void* const* d_in, const int* in_sizes, int n_in,
                              void* d_out, int out_size) {
    const float* node_feats = (const float*)d_in[0];
    const float* edge_feats = (const float*)d_in[1];
    const int* src = (const int*)d_in[2];
    const int* dst = (const int*)d_in[3];
    const float* W1a = (const float*)d_in[4];
    const float* b1a = (const float*)d_in[5];
    const float* W1b = (const float*)d_in[6];
    const float* b1b = (const float*)d_in[7];
    const float* W2a = (const float*)d_in[8];
    const float* b2a = (const float*)d_in[9];
    const float* W2b = (const float*)d_in[10];
    const float* b2b = (const float*)d_in[11];
    float* out = (float*)d_out;

    const int n_nodes = in_sizes[0] / FEAT;
    const int n_edges = in_sizes[2];

    cudaFuncSetAttribute(edge_kernel, cudaFuncAttributeMaxDynamicSharedMemorySize,
                         DYN_BYTES);
    cudaFuncSetAttribute(node_kernel, cudaFuncAttributeMaxDynamicSharedMemorySize,
                         DYN_BYTES);

    prep_weights<<<160, 256>>>(W1a, W1b, W2a, W2b);
    init_agg_kernel<<<512, 256>>>(node_feats, n_nodes * (FEAT / 4));

    int edge_blocks = (n_edges + 127) / 128;
    edge_kernel<<<edge_blocks, 256, DYN_BYTES>>>(node_feats, edge_feats, src, dst, b1a,
                                                 b1b, n_edges);

    int node_blocks = (n_nodes + 127) / 128;
    node_kernel<<<node_blocks, 256, DYN_BYTES>>>(b2a, b2b, out, n_nodes);
}

// round 10
// speedup vs baseline: 1.0327x; 1.0036x over previous
#include <cuda_runtime.h>
#include <cuda_bf16.h>

#define FEAT 128
#define MAX_NODES 50000

typedef unsigned int u32;

// ---------------- device scratch ----------------
static __device__ float g_agg[(size_t)MAX_NODES * FEAT];
// weight fragments, u32-packed per mma.m16n8k16 B-lane layout:
// idx = (((chunk*2+split)*4 + ks)*16 + nf)*64 + lane*2 + r
// -> per chunk: [hi 16KB][lo 16KB]
static __device__ __align__(16) u32 g_w1a_f[32768];  // K=256: 4 chunks
static __device__ __align__(16) u32 g_w1b_f[16384];  // K=128: 2 chunks
static __device__ __align__(16) u32 g_w2a_f[16384];
static __device__ __align__(16) u32 g_w2b_f[16384];

// ---- smem geometry (dynamic, bytes) ----
#define A_STRIDE  144
#define A_TILEB   18432
#define A_BUF     36864
#define WB0_OFF   73728
#define WB1_OFF   90112
#define DYN_BYTES 106496

// ---------------- helpers ----------------
__device__ __forceinline__ u32 smem_u32(const void* p) {
    u32 a;
    asm("{ .reg .u64 t; cvta.to.shared.u64 t, %1; cvt.u32.u64 %0, t; }" : "=r"(a) : "l"(p));
    return a;
}
__device__ __forceinline__ u32 lds32(u32 a) {
    u32 v;
    asm volatile("ld.shared.b32 %0, [%1];" : "=r"(v) : "r"(a));
    return v;
}
__device__ __forceinline__ void lds64(u32 a, u32& x, u32& y) {
    asm volatile("ld.shared.v2.b32 {%0,%1}, [%2];" : "=r"(x), "=r"(y) : "r"(a));
}
__device__ __forceinline__ void lds128(u32 a, u32* r) {
    asm volatile("ld.shared.v4.b32 {%0,%1,%2,%3}, [%4];"
                 : "=r"(r[0]), "=r"(r[1]), "=r"(r[2]), "=r"(r[3]) : "r"(a));
}
__device__ __forceinline__ void sts32(u32 a, u32 v) {
    asm volatile("st.shared.b32 [%0], %1;" ::"r"(a), "r"(v));
}
__device__ __forceinline__ void sts128(u32 a, const u32* r) {
    asm volatile("st.shared.v4.b32 [%0], {%1,%2,%3,%4};" ::"r"(a), "r"(r[0]), "r"(r[1]),
                 "r"(r[2]), "r"(r[3]));
}

__device__ __forceinline__ void mma16816(float c[4], const u32 a[4], u32 b0, u32 b1) {
    asm volatile(
        "mma.sync.aligned.m16n8k16.row.col.f32.bf16.bf16.f32 "
        "{%0,%1,%2,%3}, {%4,%5,%6,%7}, {%8,%9}, {%0,%1,%2,%3};"
        : "+f"(c[0]), "+f"(c[1]), "+f"(c[2]), "+f"(c[3])
        : "r"(a[0]), "r"(a[1]), "r"(a[2]), "r"(a[3]), "r"(b0), "r"(b1));
}

// fp32 pair -> packed bf16x2 hi + bf16x2 lo (x in low half)
__device__ __forceinline__ void split2(float x, float y, u32& h, u32& l) {
    asm("cvt.rn.bf16x2.f32 %0, %1, %2;" : "=r"(h) : "f"(y), "f"(x));
    float rx = x - __uint_as_float(h << 16);
    float ry = y - __uint_as_float(h & 0xFFFF0000u);
    asm("cvt.rn.bf16x2.f32 %0, %1, %2;" : "=r"(l) : "f"(ry), "f"(rx));
}

// convert 32 contiguous fp32 from global -> hi/lo bf16 into smem (byte addrs)
__device__ __forceinline__ void conv32(const float* __restrict__ rp, u32 dhi, u32 dlo) {
#pragma unroll
    for (int q = 0; q < 8; q++) {
        float4 f = __ldg((const float4*)rp + q);
        u32 h0, l0, h1, l1;
        split2(f.x, f.y, h0, l0);
        split2(f.z, f.w, h1, l1);
        sts32(dhi + q * 8, h0);
        sts32(dhi + q * 8 + 4, h1);
        sts32(dlo + q * 8, l0);
        sts32(dlo + q * 8 + 4, l1);
    }
}

// async-copy one 16KB weight split-tile global -> smem (256 threads)
__device__ __forceinline__ void cp_w16(const u32* __restrict__ g, u32 sB, int tid) {
#pragma unroll
    for (int i = 0; i < 4; i++) {
        u32 d = sB + (u32)(tid + i * 256) * 16;
        const u32* s = g + (tid + i * 256) * 4;
        asm volatile("cp.async.cg.shared.global [%0], [%1], 16;" ::"r"(d), "l"(s));
    }
    asm volatile("cp.async.commit_group;");
}
#define CP_WAIT0() asm volatile("cp.async.wait_group 0;" ::: "memory")

// ---- fused layer-1 GEMM chunk: acc += A_hi*B_hi + A_hi*B_lo + A_lo*B_hi ----
// warp tile 64x32 (4 mt x 4 nf); A in padded-row tile; both B splits resident.
// MMAs grouped into independent passes of 8 (no accumulator RAW within a pass).
__device__ __forceinline__ void g1_fused(u32 aHi, u32 wbh, u32 wbl, float (*acc)[4][4],
                                         int lane, int wc) {
    const u32 arow = aHi + (u32)(lane >> 2) * A_STRIDE + (lane & 3) * 4;
    const u32 blh = wbh + (u32)wc * 1024 + lane * 8;
    const u32 bll = wbl + (u32)wc * 1024 + lane * 8;
#pragma unroll
    for (int ks = 0; ks < 4; ks++) {
        u32 bh[4][2], bl[4][2];
#pragma unroll
        for (int nf = 0; nf < 4; nf++) {
            lds64(blh + ks * 4096 + nf * 256, bh[nf][0], bh[nf][1]);
            lds64(bll + ks * 4096 + nf * 256, bl[nf][0], bl[nf][1]);
        }
#pragma unroll
        for (int mg = 0; mg < 2; mg++) {  // mt groups {0,1}, {2,3}
            u32 ah[2][4], al[2][4];
#pragma unroll
            for (int m = 0; m < 2; m++) {
                u32 ab = arow + (mg * 2 + m) * (16 * A_STRIDE) + ks * 32;
                ah[m][0] = lds32(ab);
                ah[m][1] = lds32(ab + 8 * A_STRIDE);
                ah[m][2] = lds32(ab + 16);
                ah[m][3] = lds32(ab + 8 * A_STRIDE + 16);
                u32 ao = ab + A_TILEB;
                al[m][0] = lds32(ao);
                al[m][1] = lds32(ao + 8 * A_STRIDE);
                al[m][2] = lds32(ao + 16);
                al[m][3] = lds32(ao + 8 * A_STRIDE + 16);
            }
            // pass 1: hi @ B_hi (8 independent accs)
#pragma unroll
            for (int m = 0; m < 2; m++)
#pragma unroll
                for (int nf = 0; nf < 4; nf++)
                    mma16816(acc[mg * 2 + m][nf], ah[m], bh[nf][0], bh[nf][1]);
            // pass 2: hi @ B_lo
#pragma unroll
            for (int m = 0; m < 2; m++)
#pragma unroll
                for (int nf = 0; nf < 4; nf++)
                    mma16816(acc[mg * 2 + m][nf], ah[m], bl[nf][0], bl[nf][1]);
            // pass 3: lo @ B_hi
#pragma unroll
            for (int m = 0; m < 2; m++)
#pragma unroll
                for (int nf = 0; nf < 4; nf++)
                    mma16816(acc[mg * 2 + m][nf], al[m], bh[nf][0], bh[nf][1]);
        }
    }
}

// ---- fused layer-2 GEMM chunk: A from hidden fragments (LDS.128) ----
// hidden slot addr: hb + (((split*2 + wr)*4 + mt)*8 + kg)*512 + lane*16
__device__ __forceinline__ void g2_fused(u32 hb, u32 wbh, u32 wbl, float (*acc)[4][4],
                                         int lane, int wr, int wc, int kg0) {
    const u32 blh = wbh + (u32)wc * 1024 + lane * 8;
    const u32 bll = wbl + (u32)wc * 1024 + lane * 8;
#pragma unroll
    for (int ks = 0; ks < 4; ks++) {
        int kg = kg0 + ks;
        u32 bh[4][2], bl[4][2];
#pragma unroll
        for (int nf = 0; nf < 4; nf++) {
            lds64(blh + ks * 4096 + nf * 256, bh[nf][0], bh[nf][1]);
            lds64(bll + ks * 4096 + nf * 256, bl[nf][0], bl[nf][1]);
        }
#pragma unroll
        for (int mg = 0; mg < 2; mg++) {
            u32 ah[2][4], al[2][4];
#pragma unroll
            for (int m = 0; m < 2; m++) {
                int mt = mg * 2 + m;
                lds128(hb + (u32)(((wr * 4 + mt) * 8 + kg) * 512) + lane * 16, ah[m]);
                lds128(hb + (u32)((((2 + wr) * 4 + mt) * 8 + kg) * 512) + lane * 16,
                       al[m]);
            }
#pragma unroll
            for (int m = 0; m < 2; m++)
#pragma unroll
                for (int nf = 0; nf < 4; nf++)
                    mma16816(acc[mg * 2 + m][nf], ah[m], bh[nf][0], bh[nf][1]);
#pragma unroll
            for (int m = 0; m < 2; m++)
#pragma unroll
                for (int nf = 0; nf < 4; nf++)
                    mma16816(acc[mg * 2 + m][nf], ah[m], bl[nf][0], bl[nf][1]);
#pragma unroll
            for (int m = 0; m < 2; m++)
#pragma unroll
                for (int nf = 0; nf < 4; nf++)
                    mma16816(acc[mg * 2 + m][nf], al[m], bh[nf][0], bh[nf][1]);
        }
    }
}

// epilogue: relu(acc + bias) -> hidden fragments (direct A-frag layout); zero acc
__device__ __forceinline__ void epi_hidden(float (*acc)[4][4], const float* bias, u32 hb,
                                           int lane, int wr, int wc) {
    const int c2 = (lane & 3) * 2;
#pragma unroll
    for (int mt = 0; mt < 4; mt++) {
#pragma unroll
        for (int p = 0; p < 2; p++) {
            u32 h[4], l[4];
#pragma unroll
            for (int q = 0; q < 2; q++) {
                int nf = p * 2 + q;
                int n0 = wc * 32 + nf * 8 + c2;
                float v0 = fmaxf(acc[mt][nf][0] + bias[n0], 0.0f);
                float v1 = fmaxf(acc[mt][nf][1] + bias[n0 + 1], 0.0f);
                float v2 = fmaxf(acc[mt][nf][2] + bias[n0], 0.0f);
                float v3 = fmaxf(acc[mt][nf][3] + bias[n0 + 1], 0.0f);
                split2(v0, v1, h[q * 2], l[q * 2]);
                split2(v2, v3, h[q * 2 + 1], l[q * 2 + 1]);
            }
            int kg = wc * 2 + p;
            sts128(hb + (u32)(((wr * 4 + mt) * 8 + kg) * 512) + lane * 16, h);
            sts128(hb + (u32)((((2 + wr) * 4 + mt) * 8 + kg) * 512) + lane * 16, l);
        }
#pragma unroll
        for (int nf = 0; nf < 4; nf++)
#pragma unroll
            for (int j = 0; j < 4; j++) acc[mt][nf][j] = 0.0f;
    }
}

// ---------------- kernel 0: weight prep (split + fragment pack) ----------------
__device__ __forceinline__ int fidx(int ke, int n, int split) {
    int chunk = ke >> 6, ks = (ke >> 4) & 3, r = (ke >> 3) & 1, l4 = (ke >> 1) & 3;
    int nf = n >> 3, lane = (n & 7) * 4 + l4;
    return (((chunk * 2 + split) * 4 + ks) * 16 + nf) * 64 + lane * 2 + r;
}

__global__ void prep_weights(const float* __restrict__ W1a, const float* __restrict__ W1b,
                             const float* __restrict__ W2a, const float* __restrict__ W2b) {
    int total = 16384 + 3 * 8192;
    for (int i = blockIdx.x * blockDim.x + threadIdx.x; i < total;
         i += gridDim.x * blockDim.x) {
        int j = i;
        const float* W;
        u32* G;
        if (j < 16384) {
            W = W1a;
            G = g_w1a_f;
        } else {
            j -= 16384;
            int ws = j / 8192;
            j %= 8192;
            W = (ws == 0) ? W1b : (ws == 1) ? W2a : W2b;
            G = (ws == 0) ? g_w1b_f : (ws == 1) ? g_w2a_f : g_w2b_f;
        }
        int ke = (j >> 7) * 2, n = j & 127;
        float x0 = W[ke * 128 + n], x1 = W[(ke + 1) * 128 + n];
        u32 H, L;
        split2(x0, x1, H, L);
        G[fidx(ke, n, 0)] = H;
        G[fidx(ke, n, 1)] = L;
    }
}

// ---------------- kernel 1: g_agg = node_feats ----------------
__global__ void init_agg_kernel(const float* __restrict__ node_feats, int total4) {
    int i = blockIdx.x * blockDim.x + threadIdx.x;
    int stride = gridDim.x * blockDim.x;
    const float4* s = (const float4*)node_feats;
    float4* d = (float4*)g_agg;
    for (; i < total4; i += stride) d[i] = s[i];
}

// ---------------- kernel 2: edge MLP + scatter ----------------
extern __shared__ char dynraw[];

__global__ __launch_bounds__(256, 2) void edge_kernel(
    const float* __restrict__ node_feats, const float* __restrict__ edge_feats,
    const int* __restrict__ src, const int* __restrict__ dst,
    const float* __restrict__ b1a, const float* __restrict__ b1b, int n_edges) {
    __shared__ int s_src[128], s_dst[128];
    __shared__ float s_ba[FEAT], s_bb[FEAT];

    const int tid = threadIdx.x;
    const int wid = tid >> 5, lane = tid & 31;
    const int wr = wid >> 2, wc = wid & 3;
    const u32 smb = smem_u32(dynraw);
    const u32 hb = smb;  // hidden fragments alias A region
    const u32 wb0 = smb + WB0_OFF, wb1 = smb + WB1_OFF;

    const int e0 = blockIdx.x * 128;
    if (tid < 128) {
        int e = min(e0 + tid, n_edges - 1);
        s_src[tid] = __ldg(src + e);
        s_dst[tid] = __ldg(dst + e);
        s_ba[tid] = __ldg(b1a + tid);
        s_bb[tid] = __ldg(b1b + tid);
    }
    __syncthreads();

    float acc[4][4][4];
#pragma unroll
    for (int mt = 0; mt < 4; mt++)
#pragma unroll
        for (int nf = 0; nf < 4; nf++)
#pragma unroll
            for (int j = 0; j < 4; j++) acc[mt][nf][j] = 0.0f;

    const int row = tid >> 1, kh = tid & 1;
    const u32 aWarp0 = smb + (u32)wr * 64 * A_STRIDE;

    // conv chunk 0 (node_feats part 0) into A0
    {
        const float* rp = node_feats + (size_t)s_src[row] * FEAT + kh * 32;
        u32 d = smb + (u32)row * A_STRIDE + kh * 64;
        conv32(rp, d, d + A_TILEB);
    }

    // ---- layer 1: K=256, 4 chunks (fused splits, 2 syncs/chunk) ----
#pragma unroll 1
    for (int c = 0; c < 4; c++) {
        cp_w16(g_w1a_f + c * 8192, wb0, tid);         // hi_c
        cp_w16(g_w1a_f + c * 8192 + 4096, wb1, tid);  // lo_c
        if (c < 3) {  // conv next chunk into other A buffer (overlaps cp)
            const float* rp;
            int c1 = c + 1;
            if (c1 < 2)
                rp = node_feats + (size_t)s_src[row] * FEAT + c1 * 64 + kh * 32;
            else
                rp = edge_feats + (size_t)min(e0 + row, n_edges - 1) * FEAT +
                     (c1 - 2) * 64 + kh * 32;
            u32 d = smb + (u32)(c1 & 1) * A_BUF + (u32)row * A_STRIDE + kh * 64;
            conv32(rp, d, d + A_TILEB);
        }
        CP_WAIT0();
        __syncthreads();  // weights c + A(c) (and A(c+1) stores) visible
        g1_fused(aWarp0 + (u32)(c & 1) * A_BUF, wb0, wb1, acc, lane, wc);
        __syncthreads();  // all warps done reading wb/A before reuse
    }

    // ---- epilogue 1: relu -> hidden fragments (A region free after loop sync) ----
    epi_hidden(acc, s_ba, hb, lane, wr, wc);

    // ---- layer 2: K=128, 2 chunks ----
#pragma unroll 1
    for (int c = 0; c < 2; c++) {
        cp_w16(g_w1b_f + c * 8192, wb0, tid);
        cp_w16(g_w1b_f + c * 8192 + 4096, wb1, tid);
        CP_WAIT0();
        __syncthreads();  // also orders epi_hidden writes before g2 reads
        g2_fused(hb, wb0, wb1, acc, lane, wr, wc, c * 4);
        __syncthreads();
    }

    // ---- epilogue 2: scatter (acc + b1b) into g_agg ----
    const int rr = lane >> 2, c2 = (lane & 3) * 2;
#pragma unroll
    for (int mt = 0; mt < 4; mt++) {
        const int r0 = wr * 64 + mt * 16 + rr, r1 = r0 + 8;
        float* p0 = g_agg + (size_t)s_dst[r0] * FEAT;
        float* p1 = g_agg + (size_t)s_dst[r1] * FEAT;
        const bool ok0 = (e0 + r0 < n_edges), ok1 = (e0 + r1 < n_edges);
#pragma unroll
        for (int nf = 0; nf < 4; nf++) {
            int n0 = wc * 32 + nf * 8 + c2;
            if (ok0) {
                atomicAdd(p0 + n0, acc[mt][nf][0] + s_bb[n0]);
                atomicAdd(p0 + n0 + 1, acc[mt][nf][1] + s_bb[n0 + 1]);
            }
            if (ok1) {
                atomicAdd(p1 + n0, acc[mt][nf][2] + s_bb[n0]);
                atomicAdd(p1 + n0 + 1, acc[mt][nf][3] + s_bb[n0 + 1]);
            }
        }
    }
}

// ---------------- kernel 3: node MLP ----------------
__global__ __launch_bounds__(256, 2) void node_kernel(const float* __restrict__ b2a,
                                                      const float* __restrict__ b2b,
                                                      float* __restrict__ out, int n_nodes) {
    __shared__ float s_ba[FEAT], s_bb[FEAT];

    const int tid = threadIdx.x;
    const int wid = tid >> 5, lane = tid & 31;
    const int wr = wid >> 2, wc = wid & 3;
    const u32 smb = smem_u32(dynraw);
    const u32 hb = smb;
    const u32 wb0 = smb + WB0_OFF, wb1 = smb + WB1_OFF;

    const int v0 = blockIdx.x * 128;
    if (tid < 128) {
        s_ba[tid] = __ldg(b2a + tid);
        s_bb[tid] = __ldg(b2b + tid);
    }
    __syncthreads();

    float acc[4][4][4];
#pragma unroll
    for (int mt = 0; mt < 4; mt++)
#pragma unroll
        for (int nf = 0; nf < 4; nf++)
#pragma unroll
            for (int j = 0; j < 4; j++) acc[mt][nf][j] = 0.0f;

    const int row = tid >> 1, kh = tid & 1;
    const size_t grow = (size_t)min(v0 + row, n_nodes - 1) * FEAT;
    const u32 aWarp0 = smb + (u32)wr * 64 * A_STRIDE;

    {
        const float* rp = g_agg + grow + kh * 32;
        u32 d = smb + (u32)row * A_STRIDE + kh * 64;
        conv32(rp, d, d + A_TILEB);
    }

    // ---- layer 1: K=128, 2 chunks ----
#pragma unroll 1
    for (int c = 0; c < 2; c++) {
        cp_w16(g_w2a_f + c * 8192, wb0, tid);
        cp_w16(g_w2a_f + c * 8192 + 4096, wb1, tid);
        if (c == 0) {
            const float* rp = g_agg + grow + 64 + kh * 32;
            u32 d = smb + A_BUF + (u32)row * A_STRIDE + kh * 64;
            conv32(rp, d, d + A_TILEB);
        }
        CP_WAIT0();
        __syncthreads();
        g1_fused(aWarp0 + (u32)(c & 1) * A_BUF, wb0, wb1, acc, lane, wc);
        __syncthreads();
    }

    epi_hidden(acc, s_ba, hb, lane, wr, wc);

    // ---- layer 2: K=128, 2 chunks ----
#pragma unroll 1
    for (int c = 0; c < 2; c++) {
        cp_w16(g_w2b_f + c * 8192, wb0, tid);
        cp_w16(g_w2b_f + c * 8192 + 4096, wb1, tid);
        CP_WAIT0();
        __syncthreads();
        g2_fused(hb, wb0, wb1, acc, lane, wr, wc, c * 4);
        __syncthreads();
    }

    // ---- epilogue 2: out = acc + b2b ----
    const int rr = lane >> 2, c2 = (lane & 3) * 2;
#pragma unroll
    for (int mt = 0; mt < 4; mt++) {
        const int r0 = wr * 64 + mt * 16 + rr, r1 = r0 + 8;
#pragma unroll
        for (int nf = 0; nf < 4; nf++) {
            int n0 = wc * 32 + nf * 8 + c2;
            if (v0 + r0 < n_nodes) {
                float2 v = make_float2(acc[mt][nf][0] + s_bb[n0],
                                       acc[mt][nf][1] + s_bb[n0 + 1]);
                *(float2*)(out + (size_t)(v0 + r0) * FEAT + n0) = v;
            }
            if (v0 + r1 < n_nodes) {
                float2 v = make_float2(acc[mt][nf][2] + s_bb[n0],
                                       acc[mt][nf][3] + s_bb[n0 + 1]);
                *(float2*)(out + (size_t)(v0 + r1) * FEAT + n0) = v;
            }
        }
    }
}

// ---------------- launch ----------------
extern "C" void kernel_launch(void* const* d_in, const int* in_sizes, int n_in,
                              void* d_out, int out_size) {
    const float* node_feats = (const float*)d_in[0];
    const float* edge_feats = (const float*)d_in[1];
    const int* src = (const int*)d_in[2];
    const int* dst = (const int*)d_in[3];
    const float* W1a = (const float*)d_in[4];
    const float* b1a = (const float*)d_in[5];
    const float* W1b = (const float*)d_in[6];
    const float* b1b = (const float*)d_in[7];
    const float* W2a = (const float*)d_in[8];
    const float* b2a = (const float*)d_in[9];
    const float* W2b = (const float*)d_in[10];
    const float* b2b = (const float*)d_in[11];
    float* out = (float*)d_out;

    const int n_nodes = in_sizes[0] / FEAT;
    const int n_edges = in_sizes[2];

    cudaFuncSetAttribute(edge_kernel, cudaFuncAttributeMaxDynamicSharedMemorySize,
                         DYN_BYTES);
    cudaFuncSetAttribute(node_kernel, cudaFuncAttributeMaxDynamicSharedMemorySize,
                         DYN_BYTES);

    prep_weights<<<160, 256>>>(W1a, W1b, W2a, W2b);
    init_agg_kernel<<<512, 256>>>(node_feats, n_nodes * (FEAT / 4));

    int edge_blocks = (n_edges + 127) / 128;
    edge_kernel<<<edge_blocks, 256, DYN_BYTES>>>(node_feats, edge_feats, src, dst, b1a,
                                                 b1b, n_edges);

    int node_blocks = (n_nodes + 127) / 128;
    node_kernel<<<node_blocks, 256, DYN_BYTES>>>(b2a, b2b, out, n_nodes);
}

// round 11
// speedup vs baseline: 1.1513x; 1.1148x over previous
#include <cuda_runtime.h>
#include <cuda_bf16.h>

#define FEAT 128
#define MAX_NODES 50000

typedef unsigned int u32;

// ---------------- device scratch ----------------
static __device__ float g_agg[(size_t)MAX_NODES * FEAT];
// weight fragments, u32-packed per mma.m16n8k16 B-lane layout:
// idx = (((chunk*2+split)*4 + ks)*16 + nf)*64 + lane*2 + r
static __device__ __align__(16) u32 g_w1a_f[32768];  // K=256: 4 chunks
static __device__ __align__(16) u32 g_w1b_f[16384];  // K=128: 2 chunks
static __device__ __align__(16) u32 g_w2a_f[16384];
static __device__ __align__(16) u32 g_w2b_f[16384];

// ---- smem geometry (dynamic, bytes) ----
// A bf16 tile: hi @0 (128 rows x 144B), lo @18432  -> 36864
// fp32 stage:  @36864, 128 rows x 272B = 34816     -> 71680
// weights:     wb0 @71680 (16KB), wb1 @88064 (16KB)-> 104448
// hidden fragments (64KB) alias [0..65536) during layer 2.
#define A_STRIDE   144
#define A_TILEB    18432
#define STG_OFF    36864
#define STG_STRIDE 272
#define WB0_OFF    71680
#define WB1_OFF    88064
#define DYN_BYTES  104448

// ---------------- helpers ----------------
__device__ __forceinline__ u32 smem_u32(const void* p) {
    u32 a;
    asm("{ .reg .u64 t; cvta.to.shared.u64 t, %1; cvt.u32.u64 %0, t; }" : "=r"(a) : "l"(p));
    return a;
}
__device__ __forceinline__ u32 lds32(u32 a) {
    u32 v;
    asm volatile("ld.shared.b32 %0, [%1];" : "=r"(v) : "r"(a));
    return v;
}
__device__ __forceinline__ void lds64(u32 a, u32& x, u32& y) {
    asm volatile("ld.shared.v2.b32 {%0,%1}, [%2];" : "=r"(x), "=r"(y) : "r"(a));
}
__device__ __forceinline__ void lds128(u32 a, u32* r) {
    asm volatile("ld.shared.v4.b32 {%0,%1,%2,%3}, [%4];"
                 : "=r"(r[0]), "=r"(r[1]), "=r"(r[2]), "=r"(r[3]) : "r"(a));
}
__device__ __forceinline__ void sts32(u32 a, u32 v) {
    asm volatile("st.shared.b32 [%0], %1;" ::"r"(a), "r"(v));
}
__device__ __forceinline__ void sts128(u32 a, const u32* r) {
    asm volatile("st.shared.v4.b32 [%0], {%1,%2,%3,%4};" ::"r"(a), "r"(r[0]), "r"(r[1]),
                 "r"(r[2]), "r"(r[3]));
}

__device__ __forceinline__ void mma16816(float c[4], const u32 a[4], u32 b0, u32 b1) {
    asm volatile(
        "mma.sync.aligned.m16n8k16.row.col.f32.bf16.bf16.f32 "
        "{%0,%1,%2,%3}, {%4,%5,%6,%7}, {%8,%9}, {%0,%1,%2,%3};"
        : "+f"(c[0]), "+f"(c[1]), "+f"(c[2]), "+f"(c[3])
        : "r"(a[0]), "r"(a[1]), "r"(a[2]), "r"(a[3]), "r"(b0), "r"(b1));
}

// fp32 pair -> packed bf16x2 hi + bf16x2 lo (x in low half)
__device__ __forceinline__ void split2(float x, float y, u32& h, u32& l) {
    asm("cvt.rn.bf16x2.f32 %0, %1, %2;" : "=r"(h) : "f"(y), "f"(x));
    float rx = x - __uint_as_float(h << 16);
    float ry = y - __uint_as_float(h & 0xFFFF0000u);
    asm("cvt.rn.bf16x2.f32 %0, %1, %2;" : "=r"(l) : "f"(ry), "f"(rx));
}

// ---- cp.async staging: each thread stages 32 fp32 (its own convert slice) ----
__device__ __forceinline__ void stage_row(const float* __restrict__ sp, u32 sd) {
#pragma unroll
    for (int q = 0; q < 8; q++) {
        asm volatile("cp.async.cg.shared.global [%0], [%1], 16;" ::"r"(sd + q * 16),
                     "l"(sp + q * 4));
    }
    asm volatile("cp.async.commit_group;");
}

// convert own staged 32 fp32 -> hi/lo bf16 in A tile (smem -> smem)
__device__ __forceinline__ void convert_own(u32 ss, u32 dhi) {
#pragma unroll
    for (int q = 0; q < 8; q++) {
        u32 w[4];
        lds128(ss + q * 16, w);
        u32 h0, l0, h1, l1;
        split2(__uint_as_float(w[0]), __uint_as_float(w[1]), h0, l0);
        split2(__uint_as_float(w[2]), __uint_as_float(w[3]), h1, l1);
        sts32(dhi + q * 8, h0);
        sts32(dhi + q * 8 + 4, h1);
        sts32(dhi + A_TILEB + q * 8, l0);
        sts32(dhi + A_TILEB + q * 8 + 4, l1);
    }
}

// async-copy one 16KB weight split-tile global -> smem (256 threads)
__device__ __forceinline__ void cp_w16(const u32* __restrict__ g, u32 sB, int tid) {
#pragma unroll
    for (int i = 0; i < 4; i++) {
        u32 d = sB + (u32)(tid + i * 256) * 16;
        const u32* s = g + (tid + i * 256) * 4;
        asm volatile("cp.async.cg.shared.global [%0], [%1], 16;" ::"r"(d), "l"(s));
    }
    asm volatile("cp.async.commit_group;");
}
#define CP_WAIT0() asm volatile("cp.async.wait_group 0;" ::: "memory")

// ---- fused layer-1 GEMM chunk (identical to R10) ----
__device__ __forceinline__ void g1_fused(u32 aHi, u32 wbh, u32 wbl, float (*acc)[4][4],
                                         int lane, int wc) {
    const u32 arow = aHi + (u32)(lane >> 2) * A_STRIDE + (lane & 3) * 4;
    const u32 blh = wbh + (u32)wc * 1024 + lane * 8;
    const u32 bll = wbl + (u32)wc * 1024 + lane * 8;
#pragma unroll
    for (int ks = 0; ks < 4; ks++) {
        u32 bh[4][2], bl[4][2];
#pragma unroll
        for (int nf = 0; nf < 4; nf++) {
            lds64(blh + ks * 4096 + nf * 256, bh[nf][0], bh[nf][1]);
            lds64(bll + ks * 4096 + nf * 256, bl[nf][0], bl[nf][1]);
        }
#pragma unroll
        for (int mg = 0; mg < 2; mg++) {
            u32 ah[2][4], al[2][4];
#pragma unroll
            for (int m = 0; m < 2; m++) {
                u32 ab = arow + (mg * 2 + m) * (16 * A_STRIDE) + ks * 32;
                ah[m][0] = lds32(ab);
                ah[m][1] = lds32(ab + 8 * A_STRIDE);
                ah[m][2] = lds32(ab + 16);
                ah[m][3] = lds32(ab + 8 * A_STRIDE + 16);
                u32 ao = ab + A_TILEB;
                al[m][0] = lds32(ao);
                al[m][1] = lds32(ao + 8 * A_STRIDE);
                al[m][2] = lds32(ao + 16);
                al[m][3] = lds32(ao + 8 * A_STRIDE + 16);
            }
#pragma unroll
            for (int m = 0; m < 2; m++)
#pragma unroll
                for (int nf = 0; nf < 4; nf++)
                    mma16816(acc[mg * 2 + m][nf], ah[m], bh[nf][0], bh[nf][1]);
#pragma unroll
            for (int m = 0; m < 2; m++)
#pragma unroll
                for (int nf = 0; nf < 4; nf++)
                    mma16816(acc[mg * 2 + m][nf], ah[m], bl[nf][0], bl[nf][1]);
#pragma unroll
            for (int m = 0; m < 2; m++)
#pragma unroll
                for (int nf = 0; nf < 4; nf++)
                    mma16816(acc[mg * 2 + m][nf], al[m], bh[nf][0], bh[nf][1]);
        }
    }
}

// ---- fused layer-2 GEMM chunk (identical to R10) ----
__device__ __forceinline__ void g2_fused(u32 hb, u32 wbh, u32 wbl, float (*acc)[4][4],
                                         int lane, int wr, int wc, int kg0) {
    const u32 blh = wbh + (u32)wc * 1024 + lane * 8;
    const u32 bll = wbl + (u32)wc * 1024 + lane * 8;
#pragma unroll
    for (int ks = 0; ks < 4; ks++) {
        int kg = kg0 + ks;
        u32 bh[4][2], bl[4][2];
#pragma unroll
        for (int nf = 0; nf < 4; nf++) {
            lds64(blh + ks * 4096 + nf * 256, bh[nf][0], bh[nf][1]);
            lds64(bll + ks * 4096 + nf * 256, bl[nf][0], bl[nf][1]);
        }
#pragma unroll
        for (int mg = 0; mg < 2; mg++) {
            u32 ah[2][4], al[2][4];
#pragma unroll
            for (int m = 0; m < 2; m++) {
                int mt = mg * 2 + m;
                lds128(hb + (u32)(((wr * 4 + mt) * 8 + kg) * 512) + lane * 16, ah[m]);
                lds128(hb + (u32)((((2 + wr) * 4 + mt) * 8 + kg) * 512) + lane * 16,
                       al[m]);
            }
#pragma unroll
            for (int m = 0; m < 2; m++)
#pragma unroll
                for (int nf = 0; nf < 4; nf++)
                    mma16816(acc[mg * 2 + m][nf], ah[m], bh[nf][0], bh[nf][1]);
#pragma unroll
            for (int m = 0; m < 2; m++)
#pragma unroll
                for (int nf = 0; nf < 4; nf++)
                    mma16816(acc[mg * 2 + m][nf], ah[m], bl[nf][0], bl[nf][1]);
#pragma unroll
            for (int m = 0; m < 2; m++)
#pragma unroll
                for (int nf = 0; nf < 4; nf++)
                    mma16816(acc[mg * 2 + m][nf], al[m], bh[nf][0], bh[nf][1]);
        }
    }
}

// epilogue: relu(acc + bias) -> hidden fragments (identical to R10)
__device__ __forceinline__ void epi_hidden(float (*acc)[4][4], const float* bias, u32 hb,
                                           int lane, int wr, int wc) {
    const int c2 = (lane & 3) * 2;
#pragma unroll
    for (int mt = 0; mt < 4; mt++) {
#pragma unroll
        for (int p = 0; p < 2; p++) {
            u32 h[4], l[4];
#pragma unroll
            for (int q = 0; q < 2; q++) {
                int nf = p * 2 + q;
                int n0 = wc * 32 + nf * 8 + c2;
                float v0 = fmaxf(acc[mt][nf][0] + bias[n0], 0.0f);
                float v1 = fmaxf(acc[mt][nf][1] + bias[n0 + 1], 0.0f);
                float v2 = fmaxf(acc[mt][nf][2] + bias[n0], 0.0f);
                float v3 = fmaxf(acc[mt][nf][3] + bias[n0 + 1], 0.0f);
                split2(v0, v1, h[q * 2], l[q * 2]);
                split2(v2, v3, h[q * 2 + 1], l[q * 2 + 1]);
            }
            int kg = wc * 2 + p;
            sts128(hb + (u32)(((wr * 4 + mt) * 8 + kg) * 512) + lane * 16, h);
            sts128(hb + (u32)((((2 + wr) * 4 + mt) * 8 + kg) * 512) + lane * 16, l);
        }
#pragma unroll
        for (int nf = 0; nf < 4; nf++)
#pragma unroll
            for (int j = 0; j < 4; j++) acc[mt][nf][j] = 0.0f;
    }
}

// ---------------- kernel 0: weight prep ----------------
__device__ __forceinline__ int fidx(int ke, int n, int split) {
    int chunk = ke >> 6, ks = (ke >> 4) & 3, r = (ke >> 3) & 1, l4 = (ke >> 1) & 3;
    int nf = n >> 3, lane = (n & 7) * 4 + l4;
    return (((chunk * 2 + split) * 4 + ks) * 16 + nf) * 64 + lane * 2 + r;
}

__global__ void prep_weights(const float* __restrict__ W1a, const float* __restrict__ W1b,
                             const float* __restrict__ W2a, const float* __restrict__ W2b) {
    int total = 16384 + 3 * 8192;
    for (int i = blockIdx.x * blockDim.x + threadIdx.x; i < total;
         i += gridDim.x * blockDim.x) {
        int j = i;
        const float* W;
        u32* G;
        if (j < 16384) {
            W = W1a;
            G = g_w1a_f;
        } else {
            j -= 16384;
            int ws = j / 8192;
            j %= 8192;
            W = (ws == 0) ? W1b : (ws == 1) ? W2a : W2b;
            G = (ws == 0) ? g_w1b_f : (ws == 1) ? g_w2a_f : g_w2b_f;
        }
        int ke = (j >> 7) * 2, n = j & 127;
        float x0 = W[ke * 128 + n], x1 = W[(ke + 1) * 128 + n];
        u32 H, L;
        split2(x0, x1, H, L);
        G[fidx(ke, n, 0)] = H;
        G[fidx(ke, n, 1)] = L;
    }
}

// ---------------- kernel 1: g_agg = node_feats ----------------
__global__ void init_agg_kernel(const float* __restrict__ node_feats, int total4) {
    int i = blockIdx.x * blockDim.x + threadIdx.x;
    int stride = gridDim.x * blockDim.x;
    const float4* s = (const float4*)node_feats;
    float4* d = (float4*)g_agg;
    for (; i < total4; i += stride) d[i] = s[i];
}

// ---------------- kernel 2: edge MLP + scatter ----------------
extern __shared__ char dynraw[];

__global__ __launch_bounds__(256, 2) void edge_kernel(
    const float* __restrict__ node_feats, const float* __restrict__ edge_feats,
    const int* __restrict__ src, const int* __restrict__ dst,
    const float* __restrict__ b1a, const float* __restrict__ b1b, int n_edges) {
    __shared__ int s_src[128], s_dst[128];
    __shared__ float s_ba[FEAT], s_bb[FEAT];

    const int tid = threadIdx.x;
    const int wid = tid >> 5, lane = tid & 31;
    const int wr = wid >> 2, wc = wid & 3;
    const u32 smb = smem_u32(dynraw);
    const u32 hb = smb;  // hidden fragments alias A region
    const u32 wb0 = smb + WB0_OFF, wb1 = smb + WB1_OFF;

    const int e0 = blockIdx.x * 128;
    if (tid < 128) {
        int e = min(e0 + tid, n_edges - 1);
        s_src[tid] = __ldg(src + e);
        s_dst[tid] = __ldg(dst + e);
        s_ba[tid] = __ldg(b1a + tid);
        s_bb[tid] = __ldg(b1b + tid);
    }
    __syncthreads();

    float acc[4][4][4];
#pragma unroll
    for (int mt = 0; mt < 4; mt++)
#pragma unroll
        for (int nf = 0; nf < 4; nf++)
#pragma unroll
            for (int j = 0; j < 4; j++) acc[mt][nf][j] = 0.0f;

    const int row = tid & 127, hh = tid >> 7;  // staging/convert slice: 32 floats
    const u32 sstg = smb + STG_OFF + (u32)row * STG_STRIDE + hh * 128;
    const u32 sdst = smb + (u32)row * A_STRIDE + hh * 64;
    const int erow = min(e0 + row, n_edges - 1);
    const u32 aWarp0 = smb + (u32)wr * 64 * A_STRIDE;

    // row pointer for chunk c of the cat matrix
    auto rowp = [&](int c) -> const float* {
        if (c < 2) return node_feats + (size_t)s_src[row] * FEAT + c * 64 + hh * 32;
        return edge_feats + (size_t)erow * FEAT + (c - 2) * 64 + hh * 32;
    };

    // ---- prologue: stage A(0) + W(0), convert ----
    stage_row(rowp(0), sstg);
    cp_w16(g_w1a_f, wb0, tid);
    cp_w16(g_w1a_f + 4096, wb1, tid);
    CP_WAIT0();
    convert_own(sstg, sdst);
    __syncthreads();

    // ---- layer 1: K=256, 4 chunks ----
#pragma unroll 1
    for (int c = 0; c < 4; c++) {
        if (c < 3) stage_row(rowp(c + 1), sstg);  // lands during gemm
        g1_fused(aWarp0, wb0, wb1, acc, lane, wc);
        __syncthreads();  // A tile + weights free
        if (c < 3) {
            cp_w16(g_w1a_f + (c + 1) * 8192, wb0, tid);
            cp_w16(g_w1a_f + (c + 1) * 8192 + 4096, wb1, tid);
            CP_WAIT0();  // stage(c+1) + W(c+1); W is L2-hot
            convert_own(sstg, sdst);
            __syncthreads();
        }
    }

    // ---- epilogue 1: relu -> hidden fragments (A region dead after last sync) ----
    epi_hidden(acc, s_ba, hb, lane, wr, wc);

    // ---- layer 2: K=128, 2 chunks ----
#pragma unroll 1
    for (int c = 0; c < 2; c++) {
        cp_w16(g_w1b_f + c * 8192, wb0, tid);
        cp_w16(g_w1b_f + c * 8192 + 4096, wb1, tid);
        CP_WAIT0();
        __syncthreads();  // also orders epi_hidden writes before g2 reads
        g2_fused(hb, wb0, wb1, acc, lane, wr, wc, c * 4);
        __syncthreads();
    }

    // ---- epilogue 2: scatter (acc + b1b) into g_agg ----
    const int rr = lane >> 2, c2 = (lane & 3) * 2;
#pragma unroll
    for (int mt = 0; mt < 4; mt++) {
        const int r0 = wr * 64 + mt * 16 + rr, r1 = r0 + 8;
        float* p0 = g_agg + (size_t)s_dst[r0] * FEAT;
        float* p1 = g_agg + (size_t)s_dst[r1] * FEAT;
        const bool ok0 = (e0 + r0 < n_edges), ok1 = (e0 + r1 < n_edges);
#pragma unroll
        for (int nf = 0; nf < 4; nf++) {
            int n0 = wc * 32 + nf * 8 + c2;
            if (ok0) {
                atomicAdd(p0 + n0, acc[mt][nf][0] + s_bb[n0]);
                atomicAdd(p0 + n0 + 1, acc[mt][nf][1] + s_bb[n0 + 1]);
            }
            if (ok1) {
                atomicAdd(p1 + n0, acc[mt][nf][2] + s_bb[n0]);
                atomicAdd(p1 + n0 + 1, acc[mt][nf][3] + s_bb[n0 + 1]);
            }
        }
    }
}

// ---------------- kernel 3: node MLP ----------------
__global__ __launch_bounds__(256, 2) void node_kernel(const float* __restrict__ b2a,
                                                      const float* __restrict__ b2b,
                                                      float* __restrict__ out, int n_nodes) {
    __shared__ float s_ba[FEAT], s_bb[FEAT];

    const int tid = threadIdx.x;
    const int wid = tid >> 5, lane = tid & 31;
    const int wr = wid >> 2, wc = wid & 3;
    const u32 smb = smem_u32(dynraw);
    const u32 hb = smb;
    const u32 wb0 = smb + WB0_OFF, wb1 = smb + WB1_OFF;

    const int v0 = blockIdx.x * 128;
    if (tid < 128) {
        s_ba[tid] = __ldg(b2a + tid);
        s_bb[tid] = __ldg(b2b + tid);
    }
    __syncthreads();

    float acc[4][4][4];
#pragma unroll
    for (int mt = 0; mt < 4; mt++)
#pragma unroll
        for (int nf = 0; nf < 4; nf++)
#pragma unroll
            for (int j = 0; j < 4; j++) acc[mt][nf][j] = 0.0f;

    const int row = tid & 127, hh = tid >> 7;
    const u32 sstg = smb + STG_OFF + (u32)row * STG_STRIDE + hh * 128;
    const u32 sdst = smb + (u32)row * A_STRIDE + hh * 64;
    const size_t grow = (size_t)min(v0 + row, n_nodes - 1) * FEAT;
    const u32 aWarp0 = smb + (u32)wr * 64 * A_STRIDE;

    // ---- prologue ----
    stage_row(g_agg + grow + hh * 32, sstg);
    cp_w16(g_w2a_f, wb0, tid);
    cp_w16(g_w2a_f + 4096, wb1, tid);
    CP_WAIT0();
    convert_own(sstg, sdst);
    __syncthreads();

    // ---- layer 1: K=128, 2 chunks ----
#pragma unroll 1
    for (int c = 0; c < 2; c++) {
        if (c < 1) stage_row(g_agg + grow + 64 + hh * 32, sstg);
        g1_fused(aWarp0, wb0, wb1, acc, lane, wc);
        __syncthreads();
        if (c < 1) {
            cp_w16(g_w2a_f + 8192, wb0, tid);
            cp_w16(g_w2a_f + 8192 + 4096, wb1, tid);
            CP_WAIT0();
            convert_own(sstg, sdst);
            __syncthreads();
        }
    }

    epi_hidden(acc, s_ba, hb, lane, wr, wc);

    // ---- layer 2: K=128, 2 chunks ----
#pragma unroll 1
    for (int c = 0; c < 2; c++) {
        cp_w16(g_w2b_f + c * 8192, wb0, tid);
        cp_w16(g_w2b_f + c * 8192 + 4096, wb1, tid);
        CP_WAIT0();
        __syncthreads();
        g2_fused(hb, wb0, wb1, acc, lane, wr, wc, c * 4);
        __syncthreads();
    }

    // ---- epilogue 2: out = acc + b2b ----
    const int rr = lane >> 2, c2 = (lane & 3) * 2;
#pragma unroll
    for (int mt = 0; mt < 4; mt++) {
        const int r0 = wr * 64 + mt * 16 + rr, r1 = r0 + 8;
#pragma unroll
        for (int nf = 0; nf < 4; nf++) {
            int n0 = wc * 32 + nf * 8 + c2;
            if (v0 + r0 < n_nodes) {
                float2 v = make_float2(acc[mt][nf][0] + s_bb[n0],
                                       acc[mt][nf][1] + s_bb[n0 + 1]);
                *(float2*)(out + (size_t)(v0 + r0) * FEAT + n0) = v;
            }
            if (v0 + r1 < n_nodes) {
                float2 v = make_float2(acc[mt][nf][2] + s_bb[n0],
                                       acc[mt][nf][3] + s_bb[n0 + 1]);
                *(float2*)(out + (size_t)(v0 + r1) * FEAT + n0) = v;
            }
        }
    }
}

// ---------------- launch ----------------
extern "C" void kernel_launch(void* const* d_in, const int* in_sizes, int n_in,
                              void* d_out, int out_size) {
    const float* node_feats = (const float*)d_in[0];
    const float* edge_feats = (const float*)d_in[1];
    const int* src = (const int*)d_in[2];
    const int* dst = (const int*)d_in[3];
    const float* W1a = (const float*)d_in[4];
    const float* b1a = (const float*)d_in[5];
    const float* W1b = (const float*)d_in[6];
    const float* b1b = (const float*)d_in[7];
    const float* W2a = (const float*)d_in[8];
    const float* b2a = (const float*)d_in[9];
    const float* W2b = (const float*)d_in[10];
    const float* b2b = (const float*)d_in[11];
    float* out = (float*)d_out;

    const int n_nodes = in_sizes[0] / FEAT;
    const int n_edges = in_sizes[2];

    cudaFuncSetAttribute(edge_kernel, cudaFuncAttributeMaxDynamicSharedMemorySize,
                         DYN_BYTES);
    cudaFuncSetAttribute(node_kernel, cudaFuncAttributeMaxDynamicSharedMemorySize,
                         DYN_BYTES);

    prep_weights<<<160, 256>>>(W1a, W1b, W2a, W2b);
    init_agg_kernel<<<512, 256>>>(node_feats, n_nodes * (FEAT / 4));

    int edge_blocks = (n_edges + 127) / 128;
    edge_kernel<<<edge_blocks, 256, DYN_BYTES>>>(node_feats, edge_feats, src, dst, b1a,
                                                 b1b, n_edges);

    int node_blocks = (n_nodes + 127) / 128;
    node_kernel<<<node_blocks, 256, DYN_BYTES>>>(b2a, b2b, out, n_nodes);
}